// round 16
// baseline (speedup 1.0000x reference)
#include <cuda_runtime.h>
#include <cuda_bf16.h>
#include <cstdint>

// CPLSTM_20959440405049 — constant-folded solution (proof: h0=0 and the
// multiplicative gate g=(h@a)*(x_t@b) give g=0 ==> f=i=o=sigmoid(0)=0.5,
// g_t=tanh(0)=0 ==> c'=0, h'=0; induction: h_t=c_t=0 exactly for all t).
// output = dec_b broadcast over (S*B, V); (c_T, h_T) = zeros. rel_err = 0.0.
//
// Round 16: last free parameter — CTA granularity at fixed thread geometry.
// block 256 -> 512 (8192 CTAs of 512 vs 16384 of 256; identical per-thread
// addresses/stores, identical warps/SM). Probes whether L1tex store-queue
// partitioning across CTA boundaries costs anything. All other axes measured
// and closed: stream count, mapping, width, evict policy, mechanism, fusion.
// Roofline: 6.46 TB/s HBM write-path ceiling (81% of aggregate spec).

__device__ __forceinline__ void st_v8(float* p, const float4& a, const float4& b)
{
    asm volatile(
        "st.global.v8.f32 [%0], {%1,%2,%3,%4,%5,%6,%7,%8};"
        :: "l"(p),
           "f"(a.x), "f"(a.y), "f"(a.z), "f"(a.w),
           "f"(b.x), "f"(b.y), "f"(b.z), "f"(b.w)
        : "memory");
}

__global__ void __launch_bounds__(512)
cplstm_v8_kernel(const float4* __restrict__ dec_b4,
                 float* __restrict__ out,
                 int V8,            // V/8 32-byte columns per row
                 int rows,          // S*B rows
                 int chunk,         // contiguous rows per CTA-y
                 size_t tail_off,   // float offset of state tail
                 size_t tail_n8)    // 32-byte chunks in state tail
{
    const int col8 = blockIdx.x * blockDim.x + threadIdx.x;

    if (col8 < V8) {
        // Value loaded ONCE, register-resident (two float4 = one 32B chunk).
        const float4 v0 = __ldg(dec_b4 + 2 * col8);
        const float4 v1 = __ldg(dec_b4 + 2 * col8 + 1);

        const int r0 = blockIdx.y * chunk;
        int rend = r0 + chunk;
        if (rend > rows) rend = rows;

        const size_t rowf = (size_t)V8 * 8;          // floats per row
        float* p = out + (size_t)r0 * rowf + (size_t)col8 * 8;
        #pragma unroll 4
        for (int r = r0; r < rend; ++r) {
            st_v8(p, v0, v1);        // 256-bit store; steady state STG+IADD only
            p += rowf;               // +32 KB (page-local 128 KB window)
        }
    } else {
        // Overshoot threads zero the 256 KB (c_T, h_T) tail in parallel.
        const int over = gridDim.x * blockDim.x - V8;
        size_t i = (size_t)(col8 - V8) + (size_t)over * blockIdx.y;
        const size_t stride = (size_t)over * gridDim.y;
        const float4 z = make_float4(0.f, 0.f, 0.f, 0.f);
        for (; i < tail_n8; i += stride)
            st_v8(out + tail_off + i * 8, z, z);
    }
}

// Defensive generic path (only for odd sizes — not this problem's shapes).
__global__ void cplstm_generic_kernel(const float* __restrict__ dec_b,
                                      float* __restrict__ out,
                                      size_t n_total, size_t n_logits, int V)
{
    size_t i = (size_t)blockIdx.x * blockDim.x + threadIdx.x;
    const size_t stride = (size_t)gridDim.x * blockDim.x;
    for (; i < n_total; i += stride) {
        float s = (i < n_logits) ? dec_b[i % (size_t)V] : 0.f;
        out[i] = s;
    }
}

extern "C" void kernel_launch(void* const* d_in, const int* in_sizes, int n_in,
                              void* d_out, int out_size)
{
    // metadata order: inp(S,B) int32, emb(V,D), a(H,4R), b(D,4R), ct(4R,H),
    //                 dec_w(V,H), dec_b(V,)
    const float* dec_b = (const float*)d_in[6];
    float*       out   = (float*)d_out;

    const size_t SB = (size_t)in_sizes[0];   // S*B = 4096 rows
    const int    V  = in_sizes[6];           // 32000
    const size_t n_total = (size_t)out_size;
    size_t n_logits = SB * (size_t)V;
    if (n_logits > n_total) n_logits = n_total;

    const size_t n_tail = n_total - n_logits;

    // v8 path needs: V % 8 == 0, logits offset and tail both 32B-multiples.
    if ((V & 7) != 0 || (n_logits & 7) != 0 || (n_tail & 7) != 0) {
        cplstm_generic_kernel<<<148 * 8, 256>>>(dec_b, out, n_total, n_logits, V);
        return;
    }

    const int V8   = V >> 3;                 // 4000 32B columns per row
    const int rows = (int)SB;                // 4096

    // block = 512: grid.x = 8 col blocks (4096 slots >= 4000; 96 overshoot
    // threads per row-tile zero the tail). gy = 1024, chunk = 4 -> 8192 CTAs,
    // identical per-thread geometry to the measured-best 256-thread config.
    dim3 block(512, 1, 1);
    int gy = 1024;
    if (gy > rows) gy = rows;
    const int chunk = (rows + gy - 1) / gy;  // 4
    dim3 grid((V8 + 511) / 512, gy, 1);

    if ((int)grid.x * 512 == V8 && n_tail > 0) grid.x += 1;

    cplstm_v8_kernel<<<grid, block>>>(
        (const float4*)dec_b, out, V8, rows, chunk,
        n_logits, n_tail >> 3);
}

// round 17
// speedup vs baseline: 1.0057x; 1.0057x over previous
#include <cuda_runtime.h>
#include <cuda_bf16.h>
#include <cstdint>

// CPLSTM_20959440405049 — FINAL. Constant-folded solution.
//
// Proof: h0=0 and the multiplicative gate g=(h@a)*(x_t@b) give g=0 ==>
// f=i=o=sigmoid(0)=0.5, g_t=tanh(0)=0 ==> c'=0.5*0+0.5*0=0, h'=0.5*tanh(0)=0;
// by induction h_t=c_t=0 exactly for all 128 steps (exact zeros, no rounding).
// Hence output = dec_b broadcast over (S*B, V); (c_T, h_T) = zeros.
// rel_err measured 0.0 on every round.
//
// 16-round optimization summary — all axes measured and closed:
//   stream count: 2048..32768 CTAs, plateau at 16384
//   mapping: interleaved / chunk-2/4/8 / full-row -> chunk-4 best
//   store width 128/256-bit: tie | evict .cs/WB: tie | block 256/512: 256
//   mechanism LSU vs TMA bulk: LSU | fusion: single launch
// Roofline: 6.46 TB/s = 81% of 8 TB/s aggregate spec (HBM pure-write
// turnaround ceiling); issue 6.9%, L2 61%, occ 83% — all SM resources slack.
// Best wallclock 73.6 us (kernel 72.0 us) for the mandatory 524 MB store.

__device__ __forceinline__ void st_v8(float* p, const float4& a, const float4& b)
{
    asm volatile(
        "st.global.v8.f32 [%0], {%1,%2,%3,%4,%5,%6,%7,%8};"
        :: "l"(p),
           "f"(a.x), "f"(a.y), "f"(a.z), "f"(a.w),
           "f"(b.x), "f"(b.y), "f"(b.z), "f"(b.w)
        : "memory");
}

__global__ void __launch_bounds__(256)
cplstm_v8_kernel(const float4* __restrict__ dec_b4,
                 float* __restrict__ out,
                 int V8,            // V/8 32-byte columns per row
                 int rows,          // S*B rows
                 int chunk,         // contiguous rows per CTA-y
                 size_t tail_off,   // float offset of state tail
                 size_t tail_n8)    // 32-byte chunks in state tail
{
    const int col8 = blockIdx.x * blockDim.x + threadIdx.x;

    if (col8 < V8) {
        // Value loaded ONCE, register-resident (two float4 = one 32B chunk).
        const float4 v0 = __ldg(dec_b4 + 2 * col8);
        const float4 v1 = __ldg(dec_b4 + 2 * col8 + 1);

        const int r0 = blockIdx.y * chunk;
        int rend = r0 + chunk;
        if (rend > rows) rend = rows;

        const size_t rowf = (size_t)V8 * 8;          // floats per row
        float* p = out + (size_t)r0 * rowf + (size_t)col8 * 8;
        #pragma unroll 4
        for (int r = r0; r < rend; ++r) {
            st_v8(p, v0, v1);        // 256-bit store; steady state STG+IADD only
            p += rowf;               // +32 KB (page-local 128 KB window)
        }
    } else {
        // Overshoot threads zero the 256 KB (c_T, h_T) tail in parallel.
        const int over = gridDim.x * blockDim.x - V8;
        size_t i = (size_t)(col8 - V8) + (size_t)over * blockIdx.y;
        const size_t stride = (size_t)over * gridDim.y;
        const float4 z = make_float4(0.f, 0.f, 0.f, 0.f);
        for (; i < tail_n8; i += stride)
            st_v8(out + tail_off + i * 8, z, z);
    }
}

// Defensive generic path (only for odd sizes — not this problem's shapes).
__global__ void cplstm_generic_kernel(const float* __restrict__ dec_b,
                                      float* __restrict__ out,
                                      size_t n_total, size_t n_logits, int V)
{
    size_t i = (size_t)blockIdx.x * blockDim.x + threadIdx.x;
    const size_t stride = (size_t)gridDim.x * blockDim.x;
    for (; i < n_total; i += stride) {
        float s = (i < n_logits) ? dec_b[i % (size_t)V] : 0.f;
        out[i] = s;
    }
}

extern "C" void kernel_launch(void* const* d_in, const int* in_sizes, int n_in,
                              void* d_out, int out_size)
{
    // metadata order: inp(S,B) int32, emb(V,D), a(H,4R), b(D,4R), ct(4R,H),
    //                 dec_w(V,H), dec_b(V,)
    const float* dec_b = (const float*)d_in[6];
    float*       out   = (float*)d_out;

    const size_t SB = (size_t)in_sizes[0];   // S*B = 4096 rows
    const int    V  = in_sizes[6];           // 32000
    const size_t n_total = (size_t)out_size;
    size_t n_logits = SB * (size_t)V;
    if (n_logits > n_total) n_logits = n_total;

    const size_t n_tail = n_total - n_logits;

    // v8 path needs: V % 8 == 0, logits offset and tail both 32B-multiples.
    if ((V & 7) != 0 || (n_logits & 7) != 0 || (n_tail & 7) != 0) {
        cplstm_generic_kernel<<<148 * 8, 256>>>(dec_b, out, n_total, n_logits, V);
        return;
    }

    const int V8   = V >> 3;                 // 4000 32B columns per row
    const int rows = (int)SB;                // 4096

    // grid.x = 16 col blocks (4096 slots >= 4000; 96 overshoot threads per
    // row-tile zero the tail). gy = 1024, chunk = 4 -> 16384 CTAs (measured
    // optimum, bracketed flat at 8192 and 32768), 4 independent 256-bit
    // stores per main-path thread.
    dim3 block(256, 1, 1);
    int gy = 1024;
    if (gy > rows) gy = rows;
    const int chunk = (rows + gy - 1) / gy;  // 4
    dim3 grid((V8 + 255) / 256, gy, 1);

    if ((int)grid.x * 256 == V8 && n_tail > 0) grid.x += 1;

    cplstm_v8_kernel<<<grid, block>>>(
        (const float4*)dec_b, out, V8, rows, chunk,
        n_logits, n_tail >> 3);
}